// round 14
// baseline (speedup 1.0000x reference)
#include <cuda_runtime.h>
#include <cuda_fp16.h>
#include <math.h>

#define BATCH 8
#define SEQ   2048
#define EMB   1024
#define HD    128
#define MROWS (BATCH*SEQ)

// Converted inputs
__device__ __align__(16) __half g_xh[MROWS*EMB];        // x, single fp16
__device__ __align__(16) __half g_wh[3*EMB*HD];         // W hi, [p][k][n]
__device__ __align__(16) __half g_wl[3*EMB*HD];         // W lo
// Projected q (hi/lo), k (single), v (single)
__device__ __align__(16) __half g_qh[MROWS*HD];
__device__ __align__(16) __half g_ql[MROWS*HD];
__device__ __align__(16) __half g_kh[MROWS*HD];
__device__ __align__(16) __half g_vh[MROWS*HD];

// ---------------------------------------------------------------------------
// helpers
// ---------------------------------------------------------------------------
__device__ __forceinline__ unsigned packh2(float x, float y) {
    __half2 h = __floats2half2_rn(x, y);   // x in low half
    return *reinterpret_cast<unsigned*>(&h);
}
__device__ __forceinline__ void splith2(float x, float y, unsigned& hi, unsigned& lo) {
    hi = packh2(x, y);
    __half2 h = *reinterpret_cast<__half2*>(&hi);
    float2 f = __half22float2(h);
    lo = packh2(x - f.x, y - f.y);
}
__device__ __forceinline__ void ldsm4(unsigned* r, unsigned addr) {
    asm volatile("ldmatrix.sync.aligned.m8n8.x4.shared.b16 {%0,%1,%2,%3}, [%4];"
        : "=r"(r[0]), "=r"(r[1]), "=r"(r[2]), "=r"(r[3]) : "r"(addr));
}
__device__ __forceinline__ void ldsm4t(unsigned* r, unsigned addr) {
    asm volatile("ldmatrix.sync.aligned.m8n8.x4.trans.shared.b16 {%0,%1,%2,%3}, [%4];"
        : "=r"(r[0]), "=r"(r[1]), "=r"(r[2]), "=r"(r[3]) : "r"(addr));
}
__device__ __forceinline__ void mma_f16(float* d, const unsigned* a, unsigned b0, unsigned b1) {
    asm volatile("mma.sync.aligned.m16n8k16.row.col.f32.f16.f16.f32 "
        "{%0,%1,%2,%3}, {%4,%5,%6,%7}, {%8,%9}, {%0,%1,%2,%3};"
        : "+f"(d[0]), "+f"(d[1]), "+f"(d[2]), "+f"(d[3])
        : "r"(a[0]), "r"(a[1]), "r"(a[2]), "r"(a[3]), "r"(b0), "r"(b1));
}
__device__ __forceinline__ void cp16(unsigned dst, const void* src) {
    asm volatile("cp.async.ca.shared.global [%0], [%1], 16;" :: "r"(dst), "l"(src));
}

// ---------------------------------------------------------------------------
// Kernel 0a: convert x -> fp16 single.  grid 2048, 256 thr, 8 float4 each.
// ---------------------------------------------------------------------------
__global__ __launch_bounds__(256) void convert_x(const float* __restrict__ x)
{
    uint2* dst = reinterpret_cast<uint2*>(g_xh);
    const float4* src = reinterpret_cast<const float4*>(x);
    #pragma unroll
    for (int i = 0; i < 8; i++) {
        int fidx = blockIdx.x*2048 + i*256 + threadIdx.x;
        float4 v = src[fidx];
        dst[fidx] = make_uint2(packh2(v.x, v.y), packh2(v.z, v.w));
    }
}

// ---------------------------------------------------------------------------
// Kernel 0b: convert W -> fp16 hi/lo.  grid (128,3), 256 thr, 1 float4 each.
// ---------------------------------------------------------------------------
__global__ __launch_bounds__(256) void convert_w(
    const float* __restrict__ Wk,
    const float* __restrict__ Wq,
    const float* __restrict__ Wv)
{
    const int p = blockIdx.y;
    const float* W = (p == 0) ? Wq : ((p == 1) ? Wk : Wv);
    uint2* dh = reinterpret_cast<uint2*>(g_wh + (size_t)p*EMB*HD);
    uint2* dl = reinterpret_cast<uint2*>(g_wl + (size_t)p*EMB*HD);
    int fidx = blockIdx.x*256 + threadIdx.x;
    float4 v = reinterpret_cast<const float4*>(W)[fidx];
    unsigned h0, l0, h1, l1;
    splith2(v.x, v.y, h0, l0);
    splith2(v.z, v.w, h1, l1);
    dh[fidx] = make_uint2(h0, h1);
    dl[fidx] = make_uint2(l0, l1);
}

// ---------------------------------------------------------------------------
// Kernel 1: QKV projection, pure-fp16 2-product GEMM, cp.async double-buffered.
// Tile 128m x 64n, k-chunks of 64. 256 threads (8 warps, 4m x 2n; warp m32 x n32).
// grid (128, 6): p = y>>1, nBase = (y&1)*64. 2 CTAs/SM.
// Buffer (36864 B): XS [128 x 144B] @0, WH [64 x 144B] @18432, WL @27648.
// ---------------------------------------------------------------------------
#define PJ_BUF 36864
#define PJ_WHO 18432
#define PJ_WLO 27648
#define PJ_SMEM (2*PJ_BUF)

__device__ __forceinline__ void proj_stage(unsigned bufb, int t, int c,
                                           const __half* xh0, const __half* wh0,
                                           const __half* wl0)
{
    #pragma unroll
    for (int i = 0; i < 4; i++) {
        int idx = t + i*256;
        int r = idx >> 3, c8 = idx & 7;
        cp16(bufb + r*144 + c8*16, xh0 + (size_t)r*EMB + c*64 + c8*8);
    }
    #pragma unroll
    for (int i = 0; i < 2; i++) {
        int idx = t + i*256;
        int kk = idx >> 3, c8 = idx & 7;
        size_t e = (size_t)(c*64 + kk)*HD + c8*8;
        cp16(bufb + PJ_WHO + kk*144 + c8*16, wh0 + e);
        cp16(bufb + PJ_WLO + kk*144 + c8*16, wl0 + e);
    }
}

__global__ __launch_bounds__(256, 2) void qkv_proj_f16(int dummy)
{
    extern __shared__ char smraw[];
    const unsigned sb = (unsigned)__cvta_generic_to_shared(smraw);

    const int t = threadIdx.x, lane = t & 31, w = t >> 5;
    const int g = lane >> 2, tg = lane & 3;
    const int wm = w >> 1, wn = w & 1;
    const int rowBase = blockIdx.x * 128;
    const int p = blockIdx.y >> 1;
    const int nBase = (blockIdx.y & 1) * 64;

    const __half* xh0 = g_xh + (size_t)rowBase*EMB;
    const __half* wh0 = g_wh + (size_t)p*EMB*HD + nBase;
    const __half* wl0 = g_wl + (size_t)p*EMB*HD + nBase;
    __half *oh, *ol;
    bool wantLo;
    if (p == 0)      { oh = g_qh; ol = g_ql; wantLo = true;  }
    else if (p == 1) { oh = g_kh; ol = 0;    wantLo = false; }
    else             { oh = g_vh; ol = 0;    wantLo = false; }

    float acc[2][4][4];
    #pragma unroll
    for (int mf = 0; mf < 2; mf++)
        #pragma unroll
        for (int f = 0; f < 4; f++)
            #pragma unroll
            for (int j = 0; j < 4; j++) acc[mf][f][j] = 0.f;

    // prologue: stage chunk 0
    proj_stage(sb, t, 0, xh0, wh0, wl0);
    asm volatile("cp.async.commit_group;");

    for (int c = 0; c < 16; c++) {
        __syncthreads();   // all warps done with the buffer about to be overwritten
        if (c < 15) {
            proj_stage(sb + ((c + 1) & 1)*PJ_BUF, t, c + 1, xh0, wh0, wl0);
            asm volatile("cp.async.commit_group;");
            asm volatile("cp.async.wait_group 1;");
        } else {
            asm volatile("cp.async.wait_group 0;");
        }
        __syncthreads();   // current buffer visible
        const unsigned bufb = sb + (c & 1)*PJ_BUF;

        #pragma unroll
        for (int ks = 0; ks < 4; ks++) {
            unsigned ah[2][4];
            #pragma unroll
            for (int mf = 0; mf < 2; mf++) {
                unsigned aoff = ((wm*32 + mf*16 + (lane & 15))*72 + ks*16 + (lane >> 4)*8)*2;
                ldsm4(ah[mf], bufb + aoff);
            }
            unsigned bh[2][4], bl[2][4];
            #pragma unroll
            for (int nb2 = 0; nb2 < 2; nb2++) {
                int krow = ks*16 + (lane & 7) + ((lane >> 3) & 1)*8;
                int ncol = wn*32 + nb2*16 + (lane >> 4)*8;
                unsigned boff = (krow*72 + ncol)*2;
                ldsm4t(bh[nb2], bufb + PJ_WHO + boff);
                ldsm4t(bl[nb2], bufb + PJ_WLO + boff);
            }
            #pragma unroll
            for (int mf = 0; mf < 2; mf++)
                #pragma unroll
                for (int f = 0; f < 4; f++) {
                    const int nb2 = f >> 1, h = (f & 1)*2;
                    mma_f16(acc[mf][f], ah[mf], bh[nb2][h], bh[nb2][h+1]);
                    mma_f16(acc[mf][f], ah[mf], bl[nb2][h], bl[nb2][h+1]);
                }
        }
    }

    // epilogue
    #pragma unroll
    for (int mf = 0; mf < 2; mf++) {
        size_t rA = (size_t)(rowBase + wm*32 + mf*16 + g);
        #pragma unroll
        for (int f = 0; f < 4; f++) {
            int col = nBase + wn*32 + f*8 + tg*2;
            unsigned hi, lo;
            splith2(acc[mf][f][0], acc[mf][f][1], hi, lo);
            *(unsigned*)(oh + rA*HD + col) = hi;
            if (wantLo) *(unsigned*)(ol + rA*HD + col) = lo;
            splith2(acc[mf][f][2], acc[mf][f][3], hi, lo);
            *(unsigned*)(oh + (rA + 8)*HD + col) = hi;
            if (wantLo) *(unsigned*)(ol + (rA + 8)*HD + col) = lo;
        }
    }
}

// ---------------------------------------------------------------------------
// Kernel 2: causal flash attention, fp16, cp.async double-buffered, 2 CTAs/SM.
// QK: S = (Qh+Ql) * Kh (2-product).  PV: O = Ph * Vh (single).
// Qh staged via stage-buffer 0 then hoisted to registers; Ql permanent in smem.
// 256 threads (8 warps, 4m x 2n), grid 256, balanced pairing mapping.
// smem (bytes):
//   Ql @0 (17408)
//   stage s in {0,1} @17408 + s*34816 : Kh +0, Vh +17408
//   PH @87040 (9216)
//   Mx @96256 (512)  Sx @96768 (512)  m_s @97280  l_s @97536  total 97792
// ---------------------------------------------------------------------------
#define AT_QL 0
#define AT_STG 17408
#define AT_PH 87040
#define AT_MX 96256
#define AT_SX 96768
#define AT_MS 97280
#define AT_LS 97536
#define AT_SMEM 97792

__device__ __forceinline__ void stage_kv(unsigned sb, int stage, int t,
                                         const __half* kh0, const __half* vh0,
                                         int kbase)
{
    const unsigned base = sb + AT_STG + stage*34816;
    #pragma unroll
    for (int i = 0; i < 4; i++) {
        int idx = t + i*256;
        int r = idx >> 4, c8 = idx & 15;
        size_t e = (size_t)(kbase + r)*HD + c8*8;
        unsigned d = base + r*272 + c8*16;
        cp16(d,         kh0 + e);
        cp16(d + 17408, vh0 + e);
    }
}

__global__ __launch_bounds__(256, 2) void attn_f16_kernel(float* __restrict__ out)
{
    extern __shared__ char smraw[];
    const unsigned sb = (unsigned)__cvta_generic_to_shared(smraw);
    float* Mx  = (float*)(smraw + AT_MX);
    float* Sx  = (float*)(smraw + AT_SX);
    float* m_s = (float*)(smraw + AT_MS);
    float* l_s = (float*)(smraw + AT_LS);

    // Balanced tile mapping: blocks u and u+148 share an SM (classic LUT).
    // Ranks: u in [108,148) -> 0..39 (heaviest, single-CTA SMs);
    //        u in [0,108)   -> 40+u;  u in [148,256) -> 403-u.
    const int u = blockIdx.x;
    int r_;
    if (u >= 148)      r_ = 403 - u;
    else if (u >= 108) r_ = u - 108;
    else               r_ = 40 + u;
    const int b  = r_ & 7;
    const int qt = 31 - (r_ >> 3);
    const int qbase = qt * 64;

    const int t = threadIdx.x, lane = t & 31, w = t >> 5;
    const int g = lane >> 2, tg = lane & 3;
    const int wm = w >> 1, wn = w & 1;
    const int M0 = wm * 16;

    const size_t boff = (size_t)b*SEQ*HD;
    const __half *qh = g_qh + boff, *ql = g_ql + boff;
    const __half *kh = g_kh + boff;
    const __half *vh = g_vh + boff;

    // stage Q: hi through stage-buffer 0 (freed after hoist), lo permanent
    #pragma unroll
    for (int i = 0; i < 4; i++) {
        int idx = t + i*256;
        int r = idx >> 4, c8 = idx & 15;
        size_t e = (size_t)(qbase + r)*HD + c8*8;
        cp16(sb + AT_STG + r*272 + c8*16, qh + e);
        cp16(sb + AT_QL  + r*272 + c8*16, ql + e);
    }
    asm volatile("cp.async.commit_group;");
    asm volatile("cp.async.wait_group 0;");
    __syncthreads();

    // hoist Q-hi fragments (loop-invariant) into registers
    unsigned qfh[8][4];
    #pragma unroll
    for (int ks = 0; ks < 8; ks++) {
        unsigned aoff = ((M0 + (lane & 15))*136 + ks*16 + (lane >> 4)*8)*2;
        ldsm4(qfh[ks], sb + AT_STG + aoff);
    }
    if (t < 64) { m_s[t] = -1e30f; l_s[t] = 0.f; }
    __syncthreads();   // hoists done before kv0 overwrites stage 0

    stage_kv(sb, 0, t, kh, vh, 0);
    asm volatile("cp.async.commit_group;");

    float o[8][4];
    #pragma unroll
    for (int f = 0; f < 8; f++)
        #pragma unroll
        for (int j = 0; j < 4; j++) o[f][j] = 0.f;

    const float scale = 0.08838834764831845f;  // 128^-0.5

    for (int kt = 0; kt <= qt; kt++) {
        const int kbase = kt * 64;
        const int cur = kt & 1;
        const unsigned stK = sb + AT_STG + cur*34816;
        const unsigned stV = stK + 17408;

        __syncthreads();   // all warps done reading the buffer about to be overwritten
        if (kt < qt) {
            stage_kv(sb, cur ^ 1, t, kh, vh, kbase + 64);
            asm volatile("cp.async.commit_group;");
            asm volatile("cp.async.wait_group 1;");
        } else {
            asm volatile("cp.async.wait_group 0;");
        }
        __syncthreads();   // current buffer visible

        // ---- S = (Qh+Ql) Kh^T : warp m16 x n32 ----
        float s[4][4];
        #pragma unroll
        for (int f = 0; f < 4; f++)
            #pragma unroll
            for (int j = 0; j < 4; j++) s[f][j] = 0.f;

        #pragma unroll
        for (int ks = 0; ks < 8; ks++) {
            unsigned a_l[4];
            {
                unsigned aoff = ((M0 + (lane & 15))*136 + ks*16 + (lane >> 4)*8)*2;
                ldsm4(a_l, sb + AT_QL + aoff);
            }
            unsigned bh[2][4];
            #pragma unroll
            for (int nb2 = 0; nb2 < 2; nb2++) {
                int nrow = wn*32 + nb2*16 + (lane & 7) + (lane >> 4)*8;
                int koff = ks*16 + ((lane >> 3) & 1)*8;
                unsigned bo = (nrow*136 + koff)*2;
                ldsm4(bh[nb2], stK + bo);
            }
            #pragma unroll
            for (int f = 0; f < 4; f++) {
                const int nb2 = f >> 1, h = (f & 1)*2;
                mma_f16(s[f], qfh[ks], bh[nb2][h], bh[nb2][h+1]);
                mma_f16(s[f], a_l,     bh[nb2][h], bh[nb2][h+1]);
            }
        }

        // scale + causal mask
        const int rowA = qbase + M0 + g;
        const int rowB = rowA + 8;
        const bool diag = (kt == qt);
        #pragma unroll
        for (int f = 0; f < 4; f++) {
            int c = kbase + wn*32 + f*8 + tg*2;
            s[f][0] *= scale; s[f][1] *= scale; s[f][2] *= scale; s[f][3] *= scale;
            if (diag) {
                if (c     > rowA) s[f][0] = -1e30f;
                if (c + 1 > rowA) s[f][1] = -1e30f;
                if (c     > rowB) s[f][2] = -1e30f;
                if (c + 1 > rowB) s[f][3] = -1e30f;
            }
        }

        // warp-local row max, stash
        float mxA = fmaxf(fmaxf(s[0][0], s[0][1]), fmaxf(s[1][0], s[1][1]));
        mxA = fmaxf(mxA, fmaxf(fmaxf(s[2][0], s[2][1]), fmaxf(s[3][0], s[3][1])));
        float mxB = fmaxf(fmaxf(s[0][2], s[0][3]), fmaxf(s[1][2], s[1][3]));
        mxB = fmaxf(mxB, fmaxf(fmaxf(s[2][2], s[2][3]), fmaxf(s[3][2], s[3][3])));
        mxA = fmaxf(mxA, __shfl_xor_sync(0xffffffffu, mxA, 1));
        mxA = fmaxf(mxA, __shfl_xor_sync(0xffffffffu, mxA, 2));
        mxB = fmaxf(mxB, __shfl_xor_sync(0xffffffffu, mxB, 1));
        mxB = fmaxf(mxB, __shfl_xor_sync(0xffffffffu, mxB, 2));
        const float moldA = m_s[M0 + g];
        const float moldB = m_s[M0 + g + 8];
        if (tg == 0) {
            Mx[wn*64 + M0 + g]     = mxA;
            Mx[wn*64 + M0 + g + 8] = mxB;
        }
        __syncthreads();

        const float mA = fmaxf(moldA, fmaxf(Mx[M0 + g],     Mx[64 + M0 + g]));
        const float mB = fmaxf(moldB, fmaxf(Mx[M0 + g + 8], Mx[64 + M0 + g + 8]));
        const float alphaA = __expf(moldA - mA);
        const float alphaB = __expf(moldB - mB);
        if (wn == 0 && tg == 0) {
            m_s[M0 + g]     = mA;
            m_s[M0 + g + 8] = mB;
        }
        float sumA = 0.f, sumB = 0.f;
        #pragma unroll
        for (int f = 0; f < 4; f++) {
            float p0 = __expf(s[f][0] - mA);
            float p1 = __expf(s[f][1] - mA);
            float p2 = __expf(s[f][2] - mB);
            float p3 = __expf(s[f][3] - mB);
            sumA += p0 + p1; sumB += p2 + p3;
            int col = wn*32 + f*8 + tg*2;
            *(unsigned*)(smraw + AT_PH + ((M0 + g)*72 + col)*2)     = packh2(p0, p1);
            *(unsigned*)(smraw + AT_PH + ((M0 + g + 8)*72 + col)*2) = packh2(p2, p3);
        }
        sumA += __shfl_xor_sync(0xffffffffu, sumA, 1);
        sumA += __shfl_xor_sync(0xffffffffu, sumA, 2);
        sumB += __shfl_xor_sync(0xffffffffu, sumB, 1);
        sumB += __shfl_xor_sync(0xffffffffu, sumB, 2);
        if (tg == 0) {
            Sx[wn*64 + M0 + g]     = sumA;
            Sx[wn*64 + M0 + g + 8] = sumB;
        }
        __syncthreads();

        if (wn == 0 && tg == 0) {
            int r = M0 + g;
            l_s[r] = l_s[r]*alphaA + Sx[r] + Sx[64 + r];
            r += 8;
            l_s[r] = l_s[r]*alphaB + Sx[r] + Sx[64 + r];
        }

        // rescale O, then O += Ph Vh  (warp: m16 x d64)
        #pragma unroll
        for (int f = 0; f < 8; f++) {
            o[f][0] *= alphaA; o[f][1] *= alphaA;
            o[f][2] *= alphaB; o[f][3] *= alphaB;
        }
        #pragma unroll
        for (int ks2 = 0; ks2 < 4; ks2++) {
            unsigned a_h[4];
            {
                unsigned aoff = ((M0 + (lane & 15))*72 + ks2*16 + (lane >> 4)*8)*2;
                ldsm4(a_h, sb + AT_PH + aoff);
            }
            unsigned bh[2][4], bh2[2][4];
            #pragma unroll
            for (int db2 = 0; db2 < 2; db2++) {
                int srow = ks2*16 + (lane & 7) + ((lane >> 3) & 1)*8;
                int dcol = wn*64 + db2*32 + (lane >> 4)*8;
                ldsm4t(bh[db2],  stV + (srow*136 + dcol)*2);
                ldsm4t(bh2[db2], stV + (srow*136 + dcol + 16)*2);
            }
            #pragma unroll
            for (int f = 0; f < 8; f++) {
                const int db2 = f >> 2, sub = f & 3;
                const unsigned* BH = (sub < 2) ? bh[db2] : bh2[db2];
                const int h = (sub & 1)*2;
                mma_f16(o[f], a_h, BH[h], BH[h+1]);
            }
        }
    }

    // epilogue
    __syncthreads();
    {
        const float invA = 1.f / l_s[M0 + g];
        const float invB = 1.f / l_s[M0 + g + 8];
        float* Ob = out + ((size_t)b*SEQ + qbase)*HD;
        size_t rA = (size_t)(M0 + g);
        #pragma unroll
        for (int f = 0; f < 8; f++) {
            const int db2 = f >> 2, sub = f & 3;
            int col = wn*64 + db2*32 + (sub >> 1)*16 + (sub & 1)*8 + tg*2;
            *(float2*)(Ob + rA*HD + col)       = make_float2(o[f][0]*invA, o[f][1]*invA);
            *(float2*)(Ob + (rA + 8)*HD + col) = make_float2(o[f][2]*invB, o[f][3]*invB);
        }
    }
}

// ---------------------------------------------------------------------------
extern "C" void kernel_launch(void* const* d_in, const int* in_sizes, int n_in,
                              void* d_out, int out_size)
{
    const float* x  = (const float*)d_in[0];
    const float* Wk = (const float*)d_in[1];
    const float* Wq = (const float*)d_in[2];
    const float* Wv = (const float*)d_in[3];
    float* out = (float*)d_out;

    cudaFuncSetAttribute(qkv_proj_f16,
                         cudaFuncAttributeMaxDynamicSharedMemorySize, PJ_SMEM);
    cudaFuncSetAttribute(attn_f16_kernel,
                         cudaFuncAttributeMaxDynamicSharedMemorySize, AT_SMEM);

    convert_x<<<2048, 256>>>(x);
    convert_w<<<dim3(128, 3), 256>>>(Wk, Wq, Wv);
    qkv_proj_f16<<<dim3(128, 6), 256, PJ_SMEM>>>(0);
    attn_f16_kernel<<<256, 256, AT_SMEM>>>(out);
}

// round 16
// speedup vs baseline: 1.0115x; 1.0115x over previous
#include <cuda_runtime.h>
#include <cuda_fp16.h>
#include <math.h>

#define BATCH 8
#define SEQ   2048
#define EMB   1024
#define HD    128
#define MROWS (BATCH*SEQ)

// Converted inputs
__device__ __align__(16) __half g_xh[MROWS*EMB];        // x, single fp16
__device__ __align__(16) __half g_wh[3*EMB*HD];         // W hi, [p][k][n]
__device__ __align__(16) __half g_wl[3*EMB*HD];         // W lo
// Projected q (hi/lo), k (single), v (single)
__device__ __align__(16) __half g_qh[MROWS*HD];
__device__ __align__(16) __half g_ql[MROWS*HD];
__device__ __align__(16) __half g_kh[MROWS*HD];
__device__ __align__(16) __half g_vh[MROWS*HD];

// ---------------------------------------------------------------------------
// helpers
// ---------------------------------------------------------------------------
__device__ __forceinline__ unsigned packh2(float x, float y) {
    __half2 h = __floats2half2_rn(x, y);   // x in low half
    return *reinterpret_cast<unsigned*>(&h);
}
__device__ __forceinline__ void splith2(float x, float y, unsigned& hi, unsigned& lo) {
    hi = packh2(x, y);
    __half2 h = *reinterpret_cast<__half2*>(&hi);
    float2 f = __half22float2(h);
    lo = packh2(x - f.x, y - f.y);
}
__device__ __forceinline__ void ldsm4(unsigned* r, unsigned addr) {
    asm volatile("ldmatrix.sync.aligned.m8n8.x4.shared.b16 {%0,%1,%2,%3}, [%4];"
        : "=r"(r[0]), "=r"(r[1]), "=r"(r[2]), "=r"(r[3]) : "r"(addr));
}
__device__ __forceinline__ void ldsm4t(unsigned* r, unsigned addr) {
    asm volatile("ldmatrix.sync.aligned.m8n8.x4.trans.shared.b16 {%0,%1,%2,%3}, [%4];"
        : "=r"(r[0]), "=r"(r[1]), "=r"(r[2]), "=r"(r[3]) : "r"(addr));
}
__device__ __forceinline__ void mma_f16(float* d, const unsigned* a, unsigned b0, unsigned b1) {
    asm volatile("mma.sync.aligned.m16n8k16.row.col.f32.f16.f16.f32 "
        "{%0,%1,%2,%3}, {%4,%5,%6,%7}, {%8,%9}, {%0,%1,%2,%3};"
        : "+f"(d[0]), "+f"(d[1]), "+f"(d[2]), "+f"(d[3])
        : "r"(a[0]), "r"(a[1]), "r"(a[2]), "r"(a[3]), "r"(b0), "r"(b1));
}
__device__ __forceinline__ void cp16(unsigned dst, const void* src) {
    asm volatile("cp.async.ca.shared.global [%0], [%1], 16;" :: "r"(dst), "l"(src));
}

// ---------------------------------------------------------------------------
// Kernel 0a: convert x -> fp16 single.  grid 2048, 256 thr, 8 float4 each.
// ---------------------------------------------------------------------------
__global__ __launch_bounds__(256) void convert_x(const float* __restrict__ x)
{
    uint2* dst = reinterpret_cast<uint2*>(g_xh);
    const float4* src = reinterpret_cast<const float4*>(x);
    #pragma unroll
    for (int i = 0; i < 8; i++) {
        int fidx = blockIdx.x*2048 + i*256 + threadIdx.x;
        float4 v = src[fidx];
        dst[fidx] = make_uint2(packh2(v.x, v.y), packh2(v.z, v.w));
    }
}

// ---------------------------------------------------------------------------
// Kernel 0b: convert W -> fp16 hi/lo.  grid (128,3), 256 thr, 1 float4 each.
// ---------------------------------------------------------------------------
__global__ __launch_bounds__(256) void convert_w(
    const float* __restrict__ Wk,
    const float* __restrict__ Wq,
    const float* __restrict__ Wv)
{
    const int p = blockIdx.y;
    const float* W = (p == 0) ? Wq : ((p == 1) ? Wk : Wv);
    uint2* dh = reinterpret_cast<uint2*>(g_wh + (size_t)p*EMB*HD);
    uint2* dl = reinterpret_cast<uint2*>(g_wl + (size_t)p*EMB*HD);
    int fidx = blockIdx.x*256 + threadIdx.x;
    float4 v = reinterpret_cast<const float4*>(W)[fidx];
    unsigned h0, l0, h1, l1;
    splith2(v.x, v.y, h0, l0);
    splith2(v.z, v.w, h1, l1);
    dh[fidx] = make_uint2(h0, h1);
    dl[fidx] = make_uint2(l0, l1);
}

// ---------------------------------------------------------------------------
// Kernel 1: QKV projection, fp16, cp.async double-buffered, 2 CTAs/SM.
// Tile 128m x 128n (x staged ONCE per block), k-chunks of 64, 256 threads
// (8 warps, 4m x 2n; warp m32 x n64). grid (128, 3): y = proj.
// q (p=0): 2-product (W hi+lo). k,v: single product (outputs stored fp16
// single anyway, so W-lo accuracy would be discarded at the store).
// Buffer (53248 B): XS [128 x 144B] @0, WH [64 x 272B] @18432, WL @35840.
// ---------------------------------------------------------------------------
#define PJ_BUF 53248
#define PJ_WHO 18432
#define PJ_WLO 35840
#define PJ_SMEM (2*PJ_BUF)

__device__ __forceinline__ void proj_stage(unsigned bufb, int t, int c,
                                           const __half* xh0, const __half* wh0,
                                           const __half* wl0, bool wantLo)
{
    #pragma unroll
    for (int i = 0; i < 4; i++) {
        int idx = t + i*256;
        int r = idx >> 3, c8 = idx & 7;
        cp16(bufb + r*144 + c8*16, xh0 + (size_t)r*EMB + c*64 + c8*8);
    }
    #pragma unroll
    for (int i = 0; i < 4; i++) {
        int idx = t + i*256;
        int kk = idx >> 4, c8 = idx & 15;
        size_t e = (size_t)(c*64 + kk)*HD + c8*8;
        cp16(bufb + PJ_WHO + kk*272 + c8*16, wh0 + e);
        if (wantLo) cp16(bufb + PJ_WLO + kk*272 + c8*16, wl0 + e);
    }
}

__global__ __launch_bounds__(256, 2) void qkv_proj_f16(int dummy)
{
    extern __shared__ char smraw[];
    const unsigned sb = (unsigned)__cvta_generic_to_shared(smraw);

    const int t = threadIdx.x, lane = t & 31, w = t >> 5;
    const int g = lane >> 2, tg = lane & 3;
    const int wm = w >> 1, wn = w & 1;
    const int rowBase = blockIdx.x * 128;
    const int p = blockIdx.y;
    const bool wantLo = (p == 0);

    const __half* xh0 = g_xh + (size_t)rowBase*EMB;
    const __half* wh0 = g_wh + (size_t)p*EMB*HD;
    const __half* wl0 = g_wl + (size_t)p*EMB*HD;
    __half* oh = (p == 0) ? g_qh : ((p == 1) ? g_kh : g_vh);

    float acc[2][8][4];
    #pragma unroll
    for (int mf = 0; mf < 2; mf++)
        #pragma unroll
        for (int f = 0; f < 8; f++)
            #pragma unroll
            for (int j = 0; j < 4; j++) acc[mf][f][j] = 0.f;

    // prologue: stage chunk 0
    proj_stage(sb, t, 0, xh0, wh0, wl0, wantLo);
    asm volatile("cp.async.commit_group;");

    for (int c = 0; c < 16; c++) {
        __syncthreads();   // all warps done with the buffer about to be overwritten
        if (c < 15) {
            proj_stage(sb + ((c + 1) & 1)*PJ_BUF, t, c + 1, xh0, wh0, wl0, wantLo);
            asm volatile("cp.async.commit_group;");
            asm volatile("cp.async.wait_group 1;");
        } else {
            asm volatile("cp.async.wait_group 0;");
        }
        __syncthreads();   // current buffer visible
        const unsigned bufb = sb + (c & 1)*PJ_BUF;

        #pragma unroll
        for (int ks = 0; ks < 4; ks++) {
            unsigned ah[2][4];
            #pragma unroll
            for (int mf = 0; mf < 2; mf++) {
                unsigned aoff = ((wm*32 + mf*16 + (lane & 15))*72 + ks*16 + (lane >> 4)*8)*2;
                ldsm4(ah[mf], bufb + aoff);
            }
            unsigned bh[4][4];
            #pragma unroll
            for (int nb2 = 0; nb2 < 4; nb2++) {
                int krow = ks*16 + (lane & 7) + ((lane >> 3) & 1)*8;
                int ncol = wn*64 + nb2*16 + (lane >> 4)*8;
                ldsm4t(bh[nb2], bufb + PJ_WHO + (krow*136 + ncol)*2);
            }
            if (wantLo) {
                unsigned bl[4][4];
                #pragma unroll
                for (int nb2 = 0; nb2 < 4; nb2++) {
                    int krow = ks*16 + (lane & 7) + ((lane >> 3) & 1)*8;
                    int ncol = wn*64 + nb2*16 + (lane >> 4)*8;
                    ldsm4t(bl[nb2], bufb + PJ_WLO + (krow*136 + ncol)*2);
                }
                #pragma unroll
                for (int mf = 0; mf < 2; mf++)
                    #pragma unroll
                    for (int f = 0; f < 8; f++) {
                        const int nb2 = f >> 1, h = (f & 1)*2;
                        mma_f16(acc[mf][f], ah[mf], bh[nb2][h], bh[nb2][h+1]);
                        mma_f16(acc[mf][f], ah[mf], bl[nb2][h], bl[nb2][h+1]);
                    }
            } else {
                #pragma unroll
                for (int mf = 0; mf < 2; mf++)
                    #pragma unroll
                    for (int f = 0; f < 8; f++) {
                        const int nb2 = f >> 1, h = (f & 1)*2;
                        mma_f16(acc[mf][f], ah[mf], bh[nb2][h], bh[nb2][h+1]);
                    }
            }
        }
    }

    // epilogue
    #pragma unroll
    for (int mf = 0; mf < 2; mf++) {
        size_t rA = (size_t)(rowBase + wm*32 + mf*16 + g);
        #pragma unroll
        for (int f = 0; f < 8; f++) {
            int col = wn*64 + f*8 + tg*2;
            if (wantLo) {
                unsigned hi, lo;
                splith2(acc[mf][f][0], acc[mf][f][1], hi, lo);
                *(unsigned*)(g_qh + rA*HD + col) = hi;
                *(unsigned*)(g_ql + rA*HD + col) = lo;
                splith2(acc[mf][f][2], acc[mf][f][3], hi, lo);
                *(unsigned*)(g_qh + (rA + 8)*HD + col) = hi;
                *(unsigned*)(g_ql + (rA + 8)*HD + col) = lo;
            } else {
                *(unsigned*)(oh + rA*HD + col)       = packh2(acc[mf][f][0], acc[mf][f][1]);
                *(unsigned*)(oh + (rA + 8)*HD + col) = packh2(acc[mf][f][2], acc[mf][f][3]);
            }
        }
    }
}

// ---------------------------------------------------------------------------
// Kernel 2: causal flash attention (round-14, unchanged): fp16,
// cp.async double-buffered, 2 CTAs/SM, Q-hi register-hoisted, balanced pairing.
// ---------------------------------------------------------------------------
#define AT_QL 0
#define AT_STG 17408
#define AT_PH 87040
#define AT_MX 96256
#define AT_SX 96768
#define AT_MS 97280
#define AT_LS 97536
#define AT_SMEM 97792

__device__ __forceinline__ void stage_kv(unsigned sb, int stage, int t,
                                         const __half* kh0, const __half* vh0,
                                         int kbase)
{
    const unsigned base = sb + AT_STG + stage*34816;
    #pragma unroll
    for (int i = 0; i < 4; i++) {
        int idx = t + i*256;
        int r = idx >> 4, c8 = idx & 15;
        size_t e = (size_t)(kbase + r)*HD + c8*8;
        unsigned d = base + r*272 + c8*16;
        cp16(d,         kh0 + e);
        cp16(d + 17408, vh0 + e);
    }
}

__global__ __launch_bounds__(256, 2) void attn_f16_kernel(float* __restrict__ out)
{
    extern __shared__ char smraw[];
    const unsigned sb = (unsigned)__cvta_generic_to_shared(smraw);
    float* Mx  = (float*)(smraw + AT_MX);
    float* Sx  = (float*)(smraw + AT_SX);
    float* m_s = (float*)(smraw + AT_MS);
    float* l_s = (float*)(smraw + AT_LS);

    const int u = blockIdx.x;
    int r_;
    if (u >= 148)      r_ = 403 - u;
    else if (u >= 108) r_ = u - 108;
    else               r_ = 40 + u;
    const int b  = r_ & 7;
    const int qt = 31 - (r_ >> 3);
    const int qbase = qt * 64;

    const int t = threadIdx.x, lane = t & 31, w = t >> 5;
    const int g = lane >> 2, tg = lane & 3;
    const int wm = w >> 1, wn = w & 1;
    const int M0 = wm * 16;

    const size_t boff = (size_t)b*SEQ*HD;
    const __half *qh = g_qh + boff, *ql = g_ql + boff;
    const __half *kh = g_kh + boff;
    const __half *vh = g_vh + boff;

    #pragma unroll
    for (int i = 0; i < 4; i++) {
        int idx = t + i*256;
        int r = idx >> 4, c8 = idx & 15;
        size_t e = (size_t)(qbase + r)*HD + c8*8;
        cp16(sb + AT_STG + r*272 + c8*16, qh + e);
        cp16(sb + AT_QL  + r*272 + c8*16, ql + e);
    }
    asm volatile("cp.async.commit_group;");
    asm volatile("cp.async.wait_group 0;");
    __syncthreads();

    unsigned qfh[8][4];
    #pragma unroll
    for (int ks = 0; ks < 8; ks++) {
        unsigned aoff = ((M0 + (lane & 15))*136 + ks*16 + (lane >> 4)*8)*2;
        ldsm4(qfh[ks], sb + AT_STG + aoff);
    }
    if (t < 64) { m_s[t] = -1e30f; l_s[t] = 0.f; }
    __syncthreads();

    stage_kv(sb, 0, t, kh, vh, 0);
    asm volatile("cp.async.commit_group;");

    float o[8][4];
    #pragma unroll
    for (int f = 0; f < 8; f++)
        #pragma unroll
        for (int j = 0; j < 4; j++) o[f][j] = 0.f;

    const float scale = 0.08838834764831845f;

    for (int kt = 0; kt <= qt; kt++) {
        const int kbase = kt * 64;
        const int cur = kt & 1;
        const unsigned stK = sb + AT_STG + cur*34816;
        const unsigned stV = stK + 17408;

        __syncthreads();
        if (kt < qt) {
            stage_kv(sb, cur ^ 1, t, kh, vh, kbase + 64);
            asm volatile("cp.async.commit_group;");
            asm volatile("cp.async.wait_group 1;");
        } else {
            asm volatile("cp.async.wait_group 0;");
        }
        __syncthreads();

        float s[4][4];
        #pragma unroll
        for (int f = 0; f < 4; f++)
            #pragma unroll
            for (int j = 0; j < 4; j++) s[f][j] = 0.f;

        #pragma unroll
        for (int ks = 0; ks < 8; ks++) {
            unsigned a_l[4];
            {
                unsigned aoff = ((M0 + (lane & 15))*136 + ks*16 + (lane >> 4)*8)*2;
                ldsm4(a_l, sb + AT_QL + aoff);
            }
            unsigned bh[2][4];
            #pragma unroll
            for (int nb2 = 0; nb2 < 2; nb2++) {
                int nrow = wn*32 + nb2*16 + (lane & 7) + (lane >> 4)*8;
                int koff = ks*16 + ((lane >> 3) & 1)*8;
                ldsm4(bh[nb2], stK + (nrow*136 + koff)*2);
            }
            #pragma unroll
            for (int f = 0; f < 4; f++) {
                const int nb2 = f >> 1, h = (f & 1)*2;
                mma_f16(s[f], qfh[ks], bh[nb2][h], bh[nb2][h+1]);
                mma_f16(s[f], a_l,     bh[nb2][h], bh[nb2][h+1]);
            }
        }

        const int rowA = qbase + M0 + g;
        const int rowB = rowA + 8;
        const bool diag = (kt == qt);
        #pragma unroll
        for (int f = 0; f < 4; f++) {
            int c = kbase + wn*32 + f*8 + tg*2;
            s[f][0] *= scale; s[f][1] *= scale; s[f][2] *= scale; s[f][3] *= scale;
            if (diag) {
                if (c     > rowA) s[f][0] = -1e30f;
                if (c + 1 > rowA) s[f][1] = -1e30f;
                if (c     > rowB) s[f][2] = -1e30f;
                if (c + 1 > rowB) s[f][3] = -1e30f;
            }
        }

        float mxA = fmaxf(fmaxf(s[0][0], s[0][1]), fmaxf(s[1][0], s[1][1]));
        mxA = fmaxf(mxA, fmaxf(fmaxf(s[2][0], s[2][1]), fmaxf(s[3][0], s[3][1])));
        float mxB = fmaxf(fmaxf(s[0][2], s[0][3]), fmaxf(s[1][2], s[1][3]));
        mxB = fmaxf(mxB, fmaxf(fmaxf(s[2][2], s[2][3]), fmaxf(s[3][2], s[3][3])));
        mxA = fmaxf(mxA, __shfl_xor_sync(0xffffffffu, mxA, 1));
        mxA = fmaxf(mxA, __shfl_xor_sync(0xffffffffu, mxA, 2));
        mxB = fmaxf(mxB, __shfl_xor_sync(0xffffffffu, mxB, 1));
        mxB = fmaxf(mxB, __shfl_xor_sync(0xffffffffu, mxB, 2));
        const float moldA = m_s[M0 + g];
        const float moldB = m_s[M0 + g + 8];
        if (tg == 0) {
            Mx[wn*64 + M0 + g]     = mxA;
            Mx[wn*64 + M0 + g + 8] = mxB;
        }
        __syncthreads();

        const float mA = fmaxf(moldA, fmaxf(Mx[M0 + g],     Mx[64 + M0 + g]));
        const float mB = fmaxf(moldB, fmaxf(Mx[M0 + g + 8], Mx[64 + M0 + g + 8]));
        const float alphaA = __expf(moldA - mA);
        const float alphaB = __expf(moldB - mB);
        if (wn == 0 && tg == 0) {
            m_s[M0 + g]     = mA;
            m_s[M0 + g + 8] = mB;
        }
        float sumA = 0.f, sumB = 0.f;
        #pragma unroll
        for (int f = 0; f < 4; f++) {
            float p0 = __expf(s[f][0] - mA);
            float p1 = __expf(s[f][1] - mA);
            float p2 = __expf(s[f][2] - mB);
            float p3 = __expf(s[f][3] - mB);
            sumA += p0 + p1; sumB += p2 + p3;
            int col = wn*32 + f*8 + tg*2;
            *(unsigned*)(smraw + AT_PH + ((M0 + g)*72 + col)*2)     = packh2(p0, p1);
            *(unsigned*)(smraw + AT_PH + ((M0 + g + 8)*72 + col)*2) = packh2(p2, p3);
        }
        sumA += __shfl_xor_sync(0xffffffffu, sumA, 1);
        sumA += __shfl_xor_sync(0xffffffffu, sumA, 2);
        sumB += __shfl_xor_sync(0xffffffffu, sumB, 1);
        sumB += __shfl_xor_sync(0xffffffffu, sumB, 2);
        if (tg == 0) {
            Sx[wn*64 + M0 + g]     = sumA;
            Sx[wn*64 + M0 + g + 8] = sumB;
        }
        __syncthreads();

        if (wn == 0 && tg == 0) {
            int r = M0 + g;
            l_s[r] = l_s[r]*alphaA + Sx[r] + Sx[64 + r];
            r += 8;
            l_s[r] = l_s[r]*alphaB + Sx[r] + Sx[64 + r];
        }

        #pragma unroll
        for (int f = 0; f < 8; f++) {
            o[f][0] *= alphaA; o[f][1] *= alphaA;
            o[f][2] *= alphaB; o[f][3] *= alphaB;
        }
        #pragma unroll
        for (int ks2 = 0; ks2 < 4; ks2++) {
            unsigned a_h[4];
            {
                unsigned aoff = ((M0 + (lane & 15))*72 + ks2*16 + (lane >> 4)*8)*2;
                ldsm4(a_h, sb + AT_PH + aoff);
            }
            unsigned bh[2][4], bh2[2][4];
            #pragma unroll
            for (int db2 = 0; db2 < 2; db2++) {
                int srow = ks2*16 + (lane & 7) + ((lane >> 3) & 1)*8;
                int dcol = wn*64 + db2*32 + (lane >> 4)*8;
                ldsm4t(bh[db2],  stV + (srow*136 + dcol)*2);
                ldsm4t(bh2[db2], stV + (srow*136 + dcol + 16)*2);
            }
            #pragma unroll
            for (int f = 0; f < 8; f++) {
                const int db2 = f >> 2, sub = f & 3;
                const unsigned* BH = (sub < 2) ? bh[db2] : bh2[db2];
                const int h = (sub & 1)*2;
                mma_f16(o[f], a_h, BH[h], BH[h+1]);
            }
        }
    }

    __syncthreads();
    {
        const float invA = 1.f / l_s[M0 + g];
        const float invB = 1.f / l_s[M0 + g + 8];
        float* Ob = out + ((size_t)b*SEQ + qbase)*HD;
        size_t rA = (size_t)(M0 + g);
        #pragma unroll
        for (int f = 0; f < 8; f++) {
            const int db2 = f >> 2, sub = f & 3;
            int col = wn*64 + db2*32 + (sub >> 1)*16 + (sub & 1)*8 + tg*2;
            *(float2*)(Ob + rA*HD + col)       = make_float2(o[f][0]*invA, o[f][1]*invA);
            *(float2*)(Ob + (rA + 8)*HD + col) = make_float2(o[f][2]*invB, o[f][3]*invB);
        }
    }
}

// ---------------------------------------------------------------------------
extern "C" void kernel_launch(void* const* d_in, const int* in_sizes, int n_in,
                              void* d_out, int out_size)
{
    const float* x  = (const float*)d_in[0];
    const float* Wk = (const float*)d_in[1];
    const float* Wq = (const float*)d_in[2];
    const float* Wv = (const float*)d_in[3];
    float* out = (float*)d_out;

    cudaFuncSetAttribute(qkv_proj_f16,
                         cudaFuncAttributeMaxDynamicSharedMemorySize, PJ_SMEM);
    cudaFuncSetAttribute(attn_f16_kernel,
                         cudaFuncAttributeMaxDynamicSharedMemorySize, AT_SMEM);

    convert_x<<<2048, 256>>>(x);
    convert_w<<<dim3(128, 3), 256>>>(Wk, Wq, Wv);
    qkv_proj_f16<<<dim3(128, 3), 256, PJ_SMEM>>>(0);
    attn_f16_kernel<<<256, 256, AT_SMEM>>>(out);
}

// round 17
// speedup vs baseline: 1.0730x; 1.0608x over previous
#include <cuda_runtime.h>
#include <cuda_fp16.h>
#include <math.h>

#define BATCH 8
#define SEQ   2048
#define EMB   1024
#define HD    128
#define MROWS (BATCH*SEQ)

// Converted inputs
__device__ __align__(16) __half g_xh[MROWS*EMB];        // x, single fp16
__device__ __align__(16) __half g_wh[3*EMB*HD];         // W hi, [p][k][n]
__device__ __align__(16) __half g_wl[3*EMB*HD];         // W lo
// Projected q (hi/lo), k (single), v (single)
__device__ __align__(16) __half g_qh[MROWS*HD];
__device__ __align__(16) __half g_ql[MROWS*HD];
__device__ __align__(16) __half g_kh[MROWS*HD];
__device__ __align__(16) __half g_vh[MROWS*HD];

// ---------------------------------------------------------------------------
// helpers
// ---------------------------------------------------------------------------
__device__ __forceinline__ unsigned packh2(float x, float y) {
    __half2 h = __floats2half2_rn(x, y);   // x in low half
    return *reinterpret_cast<unsigned*>(&h);
}
__device__ __forceinline__ void splith2(float x, float y, unsigned& hi, unsigned& lo) {
    hi = packh2(x, y);
    __half2 h = *reinterpret_cast<__half2*>(&hi);
    float2 f = __half22float2(h);
    lo = packh2(x - f.x, y - f.y);
}
__device__ __forceinline__ void ldsm4(unsigned* r, unsigned addr) {
    asm volatile("ldmatrix.sync.aligned.m8n8.x4.shared.b16 {%0,%1,%2,%3}, [%4];"
        : "=r"(r[0]), "=r"(r[1]), "=r"(r[2]), "=r"(r[3]) : "r"(addr));
}
__device__ __forceinline__ void ldsm4t(unsigned* r, unsigned addr) {
    asm volatile("ldmatrix.sync.aligned.m8n8.x4.trans.shared.b16 {%0,%1,%2,%3}, [%4];"
        : "=r"(r[0]), "=r"(r[1]), "=r"(r[2]), "=r"(r[3]) : "r"(addr));
}
__device__ __forceinline__ void mma_f16(float* d, const unsigned* a, unsigned b0, unsigned b1) {
    asm volatile("mma.sync.aligned.m16n8k16.row.col.f32.f16.f16.f32 "
        "{%0,%1,%2,%3}, {%4,%5,%6,%7}, {%8,%9}, {%0,%1,%2,%3};"
        : "+f"(d[0]), "+f"(d[1]), "+f"(d[2]), "+f"(d[3])
        : "r"(a[0]), "r"(a[1]), "r"(a[2]), "r"(a[3]), "r"(b0), "r"(b1));
}
__device__ __forceinline__ void cp16(unsigned dst, const void* src) {
    asm volatile("cp.async.ca.shared.global [%0], [%1], 16;" :: "r"(dst), "l"(src));
}

// ---------------------------------------------------------------------------
// Kernel 0a: convert x -> fp16 single.  grid 2048, 256 thr, 8 float4 each.
// ---------------------------------------------------------------------------
__global__ __launch_bounds__(256) void convert_x(const float* __restrict__ x)
{
    uint2* dst = reinterpret_cast<uint2*>(g_xh);
    const float4* src = reinterpret_cast<const float4*>(x);
    #pragma unroll
    for (int i = 0; i < 8; i++) {
        int fidx = blockIdx.x*2048 + i*256 + threadIdx.x;
        float4 v = src[fidx];
        dst[fidx] = make_uint2(packh2(v.x, v.y), packh2(v.z, v.w));
    }
}

// ---------------------------------------------------------------------------
// Kernel 0b: convert W -> fp16 hi/lo.  grid (128,3), 256 thr, 1 float4 each.
// ---------------------------------------------------------------------------
__global__ __launch_bounds__(256) void convert_w(
    const float* __restrict__ Wk,
    const float* __restrict__ Wq,
    const float* __restrict__ Wv)
{
    const int p = blockIdx.y;
    const float* W = (p == 0) ? Wq : ((p == 1) ? Wk : Wv);
    uint2* dh = reinterpret_cast<uint2*>(g_wh + (size_t)p*EMB*HD);
    uint2* dl = reinterpret_cast<uint2*>(g_wl + (size_t)p*EMB*HD);
    int fidx = blockIdx.x*256 + threadIdx.x;
    float4 v = reinterpret_cast<const float4*>(W)[fidx];
    unsigned h0, l0, h1, l1;
    splith2(v.x, v.y, h0, l0);
    splith2(v.z, v.w, h1, l1);
    dh[fidx] = make_uint2(h0, h1);
    dl[fidx] = make_uint2(l0, l1);
}

// ---------------------------------------------------------------------------
// Kernel 1: QKV projection (round-16, unchanged): fp16, cp.async
// double-buffered, 2 CTAs/SM, 128m x 128n tiles, q 2-product, k/v single.
// ---------------------------------------------------------------------------
#define PJ_BUF 53248
#define PJ_WHO 18432
#define PJ_WLO 35840
#define PJ_SMEM (2*PJ_BUF)

__device__ __forceinline__ void proj_stage(unsigned bufb, int t, int c,
                                           const __half* xh0, const __half* wh0,
                                           const __half* wl0, bool wantLo)
{
    #pragma unroll
    for (int i = 0; i < 4; i++) {
        int idx = t + i*256;
        int r = idx >> 3, c8 = idx & 7;
        cp16(bufb + r*144 + c8*16, xh0 + (size_t)r*EMB + c*64 + c8*8);
    }
    #pragma unroll
    for (int i = 0; i < 4; i++) {
        int idx = t + i*256;
        int kk = idx >> 4, c8 = idx & 15;
        size_t e = (size_t)(c*64 + kk)*HD + c8*8;
        cp16(bufb + PJ_WHO + kk*272 + c8*16, wh0 + e);
        if (wantLo) cp16(bufb + PJ_WLO + kk*272 + c8*16, wl0 + e);
    }
}

__global__ __launch_bounds__(256, 2) void qkv_proj_f16(int dummy)
{
    extern __shared__ char smraw[];
    const unsigned sb = (unsigned)__cvta_generic_to_shared(smraw);

    const int t = threadIdx.x, lane = t & 31, w = t >> 5;
    const int g = lane >> 2, tg = lane & 3;
    const int wm = w >> 1, wn = w & 1;
    const int rowBase = blockIdx.x * 128;
    const int p = blockIdx.y;
    const bool wantLo = (p == 0);

    const __half* xh0 = g_xh + (size_t)rowBase*EMB;
    const __half* wh0 = g_wh + (size_t)p*EMB*HD;
    const __half* wl0 = g_wl + (size_t)p*EMB*HD;
    __half* oh = (p == 0) ? g_qh : ((p == 1) ? g_kh : g_vh);

    float acc[2][8][4];
    #pragma unroll
    for (int mf = 0; mf < 2; mf++)
        #pragma unroll
        for (int f = 0; f < 8; f++)
            #pragma unroll
            for (int j = 0; j < 4; j++) acc[mf][f][j] = 0.f;

    proj_stage(sb, t, 0, xh0, wh0, wl0, wantLo);
    asm volatile("cp.async.commit_group;");

    for (int c = 0; c < 16; c++) {
        __syncthreads();
        if (c < 15) {
            proj_stage(sb + ((c + 1) & 1)*PJ_BUF, t, c + 1, xh0, wh0, wl0, wantLo);
            asm volatile("cp.async.commit_group;");
            asm volatile("cp.async.wait_group 1;");
        } else {
            asm volatile("cp.async.wait_group 0;");
        }
        __syncthreads();
        const unsigned bufb = sb + (c & 1)*PJ_BUF;

        #pragma unroll
        for (int ks = 0; ks < 4; ks++) {
            unsigned ah[2][4];
            #pragma unroll
            for (int mf = 0; mf < 2; mf++) {
                unsigned aoff = ((wm*32 + mf*16 + (lane & 15))*72 + ks*16 + (lane >> 4)*8)*2;
                ldsm4(ah[mf], bufb + aoff);
            }
            unsigned bh[4][4];
            #pragma unroll
            for (int nb2 = 0; nb2 < 4; nb2++) {
                int krow = ks*16 + (lane & 7) + ((lane >> 3) & 1)*8;
                int ncol = wn*64 + nb2*16 + (lane >> 4)*8;
                ldsm4t(bh[nb2], bufb + PJ_WHO + (krow*136 + ncol)*2);
            }
            if (wantLo) {
                unsigned bl[4][4];
                #pragma unroll
                for (int nb2 = 0; nb2 < 4; nb2++) {
                    int krow = ks*16 + (lane & 7) + ((lane >> 3) & 1)*8;
                    int ncol = wn*64 + nb2*16 + (lane >> 4)*8;
                    ldsm4t(bl[nb2], bufb + PJ_WLO + (krow*136 + ncol)*2);
                }
                #pragma unroll
                for (int mf = 0; mf < 2; mf++)
                    #pragma unroll
                    for (int f = 0; f < 8; f++) {
                        const int nb2 = f >> 1, h = (f & 1)*2;
                        mma_f16(acc[mf][f], ah[mf], bh[nb2][h], bh[nb2][h+1]);
                        mma_f16(acc[mf][f], ah[mf], bl[nb2][h], bl[nb2][h+1]);
                    }
            } else {
                #pragma unroll
                for (int mf = 0; mf < 2; mf++)
                    #pragma unroll
                    for (int f = 0; f < 8; f++) {
                        const int nb2 = f >> 1, h = (f & 1)*2;
                        mma_f16(acc[mf][f], ah[mf], bh[nb2][h], bh[nb2][h+1]);
                    }
            }
        }
    }

    #pragma unroll
    for (int mf = 0; mf < 2; mf++) {
        size_t rA = (size_t)(rowBase + wm*32 + mf*16 + g);
        #pragma unroll
        for (int f = 0; f < 8; f++) {
            int col = wn*64 + f*8 + tg*2;
            if (wantLo) {
                unsigned hi, lo;
                splith2(acc[mf][f][0], acc[mf][f][1], hi, lo);
                *(unsigned*)(g_qh + rA*HD + col) = hi;
                *(unsigned*)(g_ql + rA*HD + col) = lo;
                splith2(acc[mf][f][2], acc[mf][f][3], hi, lo);
                *(unsigned*)(g_qh + (rA + 8)*HD + col) = hi;
                *(unsigned*)(g_ql + (rA + 8)*HD + col) = lo;
            } else {
                *(unsigned*)(oh + rA*HD + col)       = packh2(acc[mf][f][0], acc[mf][f][1]);
                *(unsigned*)(oh + (rA + 8)*HD + col) = packh2(acc[mf][f][2], acc[mf][f][3]);
            }
        }
    }
}

// ---------------------------------------------------------------------------
// Kernel 2: causal flash attention, FA2-style register softmax.
// BQ=64, 4 warps x 32 = 128 threads; each warp owns m16 rows, full n64 / d128.
// QK: S = (Qh+Ql) Kh^T (2-product). Softmax warp-local (m/l in registers,
// quad shuffles only). P converted in registers to PV A-fragments (no smem).
// PV: O = P Vh (single product). cp.async double-buffered K/V.
// smem: two stages @ s*34816: Kh +0, Vh +17408. total 69632 -> 2 CTAs/SM.
// ---------------------------------------------------------------------------
#define AT_STG 0
#define AT_SMEM 69632

__device__ __forceinline__ void stage_kv(unsigned sb, int stage, int t,
                                         const __half* kh0, const __half* vh0,
                                         int kbase)
{
    const unsigned base = sb + AT_STG + stage*34816;
    #pragma unroll
    for (int i = 0; i < 8; i++) {
        int idx = t + i*128;
        int r = idx >> 4, c8 = idx & 15;
        size_t e = (size_t)(kbase + r)*HD + c8*8;
        unsigned d = base + r*272 + c8*16;
        cp16(d,         kh0 + e);
        cp16(d + 17408, vh0 + e);
    }
}

__global__ __launch_bounds__(128, 2) void attn_f16_kernel(float* __restrict__ out)
{
    extern __shared__ char smraw[];
    const unsigned sb = (unsigned)__cvta_generic_to_shared(smraw);

    // Balanced tile mapping (blocks u and u+148 share an SM).
    const int u = blockIdx.x;
    int r_;
    if (u >= 148)      r_ = 403 - u;
    else if (u >= 108) r_ = u - 108;
    else               r_ = 40 + u;
    const int b  = r_ & 7;
    const int qt = 31 - (r_ >> 3);
    const int qbase = qt * 64;

    const int t = threadIdx.x, lane = t & 31, w = t >> 5;
    const int g = lane >> 2, tg = lane & 3;
    const int M0 = w * 16;

    const size_t boff = (size_t)b*SEQ*HD;
    const __half *qh = g_qh + boff, *ql = g_ql + boff;
    const __half *kh = g_kh + boff;
    const __half *vh = g_vh + boff;

    // stage Q (hi @ stage0+0, lo @ stage0+17408), then hoist to registers
    #pragma unroll
    for (int i = 0; i < 8; i++) {
        int idx = t + i*128;
        int r = idx >> 4, c8 = idx & 15;
        size_t e = (size_t)(qbase + r)*HD + c8*8;
        cp16(sb + AT_STG + r*272 + c8*16,         qh + e);
        cp16(sb + AT_STG + 17408 + r*272 + c8*16, ql + e);
    }
    asm volatile("cp.async.commit_group;");
    asm volatile("cp.async.wait_group 0;");
    __syncthreads();

    unsigned qfh[8][4], qfl[8][4];
    #pragma unroll
    for (int ks = 0; ks < 8; ks++) {
        unsigned aoff = ((M0 + (lane & 15))*136 + ks*16 + (lane >> 4)*8)*2;
        ldsm4(qfh[ks], sb + AT_STG + aoff);
        ldsm4(qfl[ks], sb + AT_STG + 17408 + aoff);
    }
    __syncthreads();   // hoists done before kv0 overwrites stage 0

    stage_kv(sb, 0, t, kh, vh, 0);
    asm volatile("cp.async.commit_group;");

    float o[16][4];
    #pragma unroll
    for (int f = 0; f < 16; f++)
        #pragma unroll
        for (int j = 0; j < 4; j++) o[f][j] = 0.f;
    float m_A = -1e30f, m_B = -1e30f, l_A = 0.f, l_B = 0.f;

    const float scale = 0.08838834764831845f;  // 128^-0.5

    for (int kt = 0; kt <= qt; kt++) {
        const int kbase = kt * 64;
        const int cur = kt & 1;
        const unsigned stK = sb + AT_STG + cur*34816;
        const unsigned stV = stK + 17408;

        __syncthreads();   // all warps done reading buffer about to be overwritten
        if (kt < qt) {
            stage_kv(sb, cur ^ 1, t, kh, vh, kbase + 64);
            asm volatile("cp.async.commit_group;");
            asm volatile("cp.async.wait_group 1;");
        } else {
            asm volatile("cp.async.wait_group 0;");
        }
        __syncthreads();   // current buffer visible

        // ---- S = (Qh+Ql) Kh^T : warp m16 x n64 ----
        float s[8][4];
        #pragma unroll
        for (int f = 0; f < 8; f++)
            #pragma unroll
            for (int j = 0; j < 4; j++) s[f][j] = 0.f;

        #pragma unroll
        for (int ks = 0; ks < 8; ks++) {
            unsigned bh[4][4];
            #pragma unroll
            for (int nb2 = 0; nb2 < 4; nb2++) {
                int nrow = nb2*16 + (lane & 7) + (lane >> 4)*8;
                int koff = ks*16 + ((lane >> 3) & 1)*8;
                ldsm4(bh[nb2], stK + (nrow*136 + koff)*2);
            }
            #pragma unroll
            for (int f = 0; f < 8; f++) {
                const int nb2 = f >> 1, h = (f & 1)*2;
                mma_f16(s[f], qfh[ks], bh[nb2][h], bh[nb2][h+1]);
                mma_f16(s[f], qfl[ks], bh[nb2][h], bh[nb2][h+1]);
            }
        }

        // scale + causal mask
        const int rowA = qbase + M0 + g;
        const int rowB = rowA + 8;
        const bool diag = (kt == qt);
        #pragma unroll
        for (int f = 0; f < 8; f++) {
            int c = kbase + f*8 + tg*2;
            s[f][0] *= scale; s[f][1] *= scale; s[f][2] *= scale; s[f][3] *= scale;
            if (diag) {
                if (c     > rowA) s[f][0] = -1e30f;
                if (c + 1 > rowA) s[f][1] = -1e30f;
                if (c     > rowB) s[f][2] = -1e30f;
                if (c + 1 > rowB) s[f][3] = -1e30f;
            }
        }

        // ---- warp-local softmax (registers + quad shuffles only) ----
        float mxA = -1e30f, mxB = -1e30f;
        #pragma unroll
        for (int f = 0; f < 8; f++) {
            mxA = fmaxf(mxA, fmaxf(s[f][0], s[f][1]));
            mxB = fmaxf(mxB, fmaxf(s[f][2], s[f][3]));
        }
        mxA = fmaxf(mxA, __shfl_xor_sync(0xffffffffu, mxA, 1));
        mxA = fmaxf(mxA, __shfl_xor_sync(0xffffffffu, mxA, 2));
        mxB = fmaxf(mxB, __shfl_xor_sync(0xffffffffu, mxB, 1));
        mxB = fmaxf(mxB, __shfl_xor_sync(0xffffffffu, mxB, 2));
        const float mA = fmaxf(m_A, mxA);
        const float mB = fmaxf(m_B, mxB);
        const float alphaA = __expf(m_A - mA);
        const float alphaB = __expf(m_B - mB);

        unsigned pA[8], pB[8];
        float sumA = 0.f, sumB = 0.f;
        #pragma unroll
        for (int f = 0; f < 8; f++) {
            float p0 = __expf(s[f][0] - mA);
            float p1 = __expf(s[f][1] - mA);
            float p2 = __expf(s[f][2] - mB);
            float p3 = __expf(s[f][3] - mB);
            sumA += p0 + p1; sumB += p2 + p3;
            pA[f] = packh2(p0, p1);
            pB[f] = packh2(p2, p3);
        }
        sumA += __shfl_xor_sync(0xffffffffu, sumA, 1);
        sumA += __shfl_xor_sync(0xffffffffu, sumA, 2);
        sumB += __shfl_xor_sync(0xffffffffu, sumB, 1);
        sumB += __shfl_xor_sync(0xffffffffu, sumB, 2);
        l_A = l_A*alphaA + sumA;  m_A = mA;
        l_B = l_B*alphaB + sumB;  m_B = mB;

        // rescale O, then O += P Vh  (P as register A-fragments)
        #pragma unroll
        for (int f = 0; f < 16; f++) {
            o[f][0] *= alphaA; o[f][1] *= alphaA;
            o[f][2] *= alphaB; o[f][3] *= alphaB;
        }
        #pragma unroll
        for (int kp = 0; kp < 4; kp++) {
            unsigned pa[4] = { pA[2*kp], pB[2*kp], pA[2*kp + 1], pB[2*kp + 1] };
            unsigned vb[8][4];
            #pragma unroll
            for (int vb2 = 0; vb2 < 8; vb2++) {
                int srow = kp*16 + (lane & 7) + ((lane >> 3) & 1)*8;
                int dcol = vb2*16 + (lane >> 4)*8;
                ldsm4t(vb[vb2], stV + (srow*136 + dcol)*2);
            }
            #pragma unroll
            for (int fo = 0; fo < 16; fo++) {
                const int vb2 = fo >> 1, h = (fo & 1)*2;
                mma_f16(o[fo], pa, vb[vb2][h], vb[vb2][h+1]);
            }
        }
    }

    // epilogue (all-register; no sync needed)
    {
        const float invA = 1.f / l_A;
        const float invB = 1.f / l_B;
        float* Ob = out + ((size_t)b*SEQ + qbase)*HD;
        size_t rA = (size_t)(M0 + g);
        #pragma unroll
        for (int fo = 0; fo < 16; fo++) {
            int col = fo*8 + tg*2;
            *(float2*)(Ob + rA*HD + col)       = make_float2(o[fo][0]*invA, o[fo][1]*invA);
            *(float2*)(Ob + (rA + 8)*HD + col) = make_float2(o[fo][2]*invB, o[fo][3]*invB);
        }
    }
}

// ---------------------------------------------------------------------------
extern "C" void kernel_launch(void* const* d_in, const int* in_sizes, int n_in,
                              void* d_out, int out_size)
{
    const float* x  = (const float*)d_in[0];
    const float* Wk = (const float*)d_in[1];
    const float* Wq = (const float*)d_in[2];
    const float* Wv = (const float*)d_in[3];
    float* out = (float*)d_out;

    cudaFuncSetAttribute(qkv_proj_f16,
                         cudaFuncAttributeMaxDynamicSharedMemorySize, PJ_SMEM);
    cudaFuncSetAttribute(attn_f16_kernel,
                         cudaFuncAttributeMaxDynamicSharedMemorySize, AT_SMEM);

    convert_x<<<2048, 256>>>(x);
    convert_w<<<dim3(128, 3), 256>>>(Wk, Wq, Wv);
    qkv_proj_f16<<<dim3(128, 3), 256, PJ_SMEM>>>(0);
    attn_f16_kernel<<<256, 128, AT_SMEM>>>(out);
}